// round 7
// baseline (speedup 1.0000x reference)
#include <cuda_runtime.h>
#include <math.h>
#include <stdint.h>

// Problem constants
#define NTOK   65536
#define DIM    256
#define KCODE  1024
#define HW     1024
#define MT     256          // tokens per CTA
#define NC     64           // codes per B chunk
#define CHUNKS 16
#define MARGIN 8.0e-4f
#define APAD   132          // u32 (bf16x2) per A row (128 + 4 pad) -> 528B stride
#define BPAD   132          // u32 (bf16x2) per B row
#define BUFB   (NC*BPAD*4)  // 33792 bytes per B buffer

// smem byte offsets
#define OFF_A     0                             // 256*132*4 = 135168
#define OFF_B     135168                        // 2*64*132*4 = 67584
#define OFF_CN    202752                        // 1024 f32
#define OFF_CANDV 206848                        // 256*8 f32
#define OFF_CANDI 215040                        // 256*8 i32
#define OFF_THR   223232                        // 256 u32
#define OFF_CNT   224256                        // 256 u32
#define OFF_XN    225280                        // 256 f32
#define OFF_RED   226304                        // 256 f32
#define SMEM_TOTAL 227328

__device__ __align__(16) float    g_cnorm[KCODE];
__device__ __align__(16) uint32_t g_cbf[KCODE * DIM / 2];   // bf16 codebook
__device__ int    g_idx[NTOK];
__device__ int    g_counts[KCODE];
__device__ double g_loss;

// ---------------- helpers ----------------
__device__ __forceinline__ uint32_t smem_u32(const void* p) {
    uint32_t a;
    asm("{ .reg .u64 t; cvta.to.shared.u64 t, %1; cvt.u32.u64 %0, t; }" : "=r"(a) : "l"(p));
    return a;
}
__device__ __forceinline__ uint32_t fkey(float f) {
    uint32_t u = __float_as_uint(f);
    return u ^ (uint32_t)(((int32_t)u >> 31) | 0x80000000);
}
__device__ __forceinline__ float fdec(uint32_t k) {
    uint32_t u = (k & 0x80000000u) ? (k ^ 0x80000000u) : ~k;
    return __uint_as_float(u);
}
__device__ __forceinline__ uint32_t packbf(float lo, float hi) {
    uint32_t r;
    asm("cvt.rn.bf16x2.f32 %0, %1, %2;" : "=r"(r) : "f"(hi), "f"(lo));
    return r;
}
__device__ __forceinline__ void mma_bf16(float* c, uint32_t a0, uint32_t a1,
                                         uint32_t a2, uint32_t a3,
                                         uint32_t b0, uint32_t b1) {
    asm volatile("mma.sync.aligned.m16n8k16.row.col.f32.bf16.bf16.f32 "
                 "{%0,%1,%2,%3}, {%4,%5,%6,%7}, {%8,%9}, {%0,%1,%2,%3};"
                 : "+f"(c[0]), "+f"(c[1]), "+f"(c[2]), "+f"(c[3])
                 : "r"(a0), "r"(a1), "r"(a2), "r"(a3), "r"(b0), "r"(b1));
}
__device__ __forceinline__ void ldsm4(uint32_t* r, uint32_t addr) {
    asm volatile("ldmatrix.sync.aligned.m8n8.x4.shared.b16 {%0,%1,%2,%3}, [%4];"
                 : "=r"(r[0]), "=r"(r[1]), "=r"(r[2]), "=r"(r[3]) : "r"(addr));
}
__device__ __forceinline__ void cp_async16(uint32_t dst, const void* src) {
    asm volatile("cp.async.cg.shared.global [%0], [%1], 16;"
                 :: "r"(dst), "l"(__cvta_generic_to_global(src)) : "memory");
}
#define CP_COMMIT() asm volatile("cp.async.commit_group;" ::: "memory")
#define CP_WAIT1()  asm volatile("cp.async.wait_group 1;" ::: "memory")
#define CP_WAIT0()  asm volatile("cp.async.wait_group 0;" ::: "memory")

// ---------------------------------------------------------------------------
// Kernel A: sequential fp32 codebook norms (bit-identical to ref reduce) +
// bf16 codebook conversion + zero accumulators.
// ---------------------------------------------------------------------------
__global__ void prep_kernel(const float* __restrict__ cb) {
    int gid = blockIdx.x * blockDim.x + threadIdx.x;
    if (gid < KCODE) {
        const float4* row = (const float4*)(cb + (size_t)gid * DIM);
        uint32_t* dst = g_cbf + (size_t)gid * (DIM / 2);
        float s = 0.f;
        #pragma unroll 4
        for (int q = 0; q < DIM / 4; q++) {
            float4 v = row[q];
            s = __fadd_rn(s, __fmul_rn(v.x, v.x));
            s = __fadd_rn(s, __fmul_rn(v.y, v.y));
            s = __fadd_rn(s, __fmul_rn(v.z, v.z));
            s = __fadd_rn(s, __fmul_rn(v.w, v.w));
            dst[2 * q]     = packbf(v.x, v.y);
            dst[2 * q + 1] = packbf(v.z, v.w);
        }
        g_cnorm[gid] = s;
        g_counts[gid] = 0;
    }
    if (gid == 0) g_loss = 0.0;
}

// ---------------------------------------------------------------------------
// Main fused kernel: bf16 mma.sync (ldmatrix operands) + register candidate
// rings + exact fp32 rescue + argmin + histogram + loss.
// 256 CTAs x 256 threads.
// ---------------------------------------------------------------------------
__global__ __launch_bounds__(256, 1)
void argmin_kernel(const float* __restrict__ x, const float* __restrict__ cb,
                   float* __restrict__ out_idx_f) {
    extern __shared__ char smem[];
    uint32_t* Au    = (uint32_t*)(smem + OFF_A);
    float*    cnS   = (float*)(smem + OFF_CN);
    float*    candv = (float*)(smem + OFF_CANDV);
    int*      candi = (int*)(smem + OFF_CANDI);
    uint32_t* thrS  = (uint32_t*)(smem + OFF_THR);
    uint32_t* cntS  = (uint32_t*)(smem + OFF_CNT);
    float*    xnS   = (float*)(smem + OFF_XN);
    float*    redS  = (float*)(smem + OFF_RED);

    const uint32_t sbA = smem_u32(smem + OFF_A);
    const uint32_t sbB = smem_u32(smem + OFF_B);

    const int tid  = threadIdx.x;
    const int lane = tid & 31;
    const int wid  = tid >> 5;
    const int g    = lane >> 2;
    const int t    = lane & 3;

    const int t0   = blockIdx.x * MT;
    const int b    = t0 >> 10;
    const int tloc = t0 & (HW - 1);
    const float* xb = x + (size_t)b * DIM * HW + tloc;   // (d,m): xb[d*HW+m]

    // ---- issue B chunk 0 cp.async (overlaps A pass) ----
    {
        #pragma unroll
        for (int it = 0; it < 8; it++) {
            int e = tid + 256 * it;               // 0..2047
            int n = e >> 5, s4 = e & 31;          // 64 rows x 32 x 16B = full 32KB
            cp_async16(sbB + (uint32_t)(n * (BPAD * 4) + s4 * 16),
                       g_cbf + (size_t)n * (DIM / 2) + s4 * 4);
        }
        CP_COMMIT();
    }

    // ---- per-token init ----
    thrS[tid] = 0xFF800000u;    // fkey(+inf)
    cntS[tid] = 0;
    ((float4*)cnS)[tid] = ((const float4*)g_cnorm)[tid];

    // ---- A pass: exact sequential xn + bf16 A tile ----
    {
        const float* xp = xb + tid;               // token m = tid
        float xn = 0.f, prev = 0.f;
        #pragma unroll 8
        for (int d = 0; d < DIM; d++) {
            float v = xp[(size_t)d * HW];
            xn = __fadd_rn(xn, __fmul_rn(v, v));
            if (d & 1) Au[tid * APAD + (d >> 1)] = packbf(prev, v);
            else prev = v;
        }
        xnS[tid] = xn;
    }
    __syncthreads();

    // ---- MMA setup ----
    const int warpM = wid;                        // rows warpM*32 .. +31
    const int rowbase = warpM * 32 + g;           // rows rowbase + 8*ri, ri=0..3

    // ldmatrix per-lane addresses:
    // A tiles (m16k16): rows (l&15), half (l>>4) selects k-lo/k-hi 16B
    uint32_t aA0 = sbA + (uint32_t)((warpM * 32 + (lane & 15)) * (APAD * 4) + (lane >> 4) * 16);
    uint32_t aA1 = aA0 + 16u * (APAD * 4);
    // B pairs (two n8k16 tiles per x4): n = 16p + 8*(l>>4) + (l&7), half (l>>3)&1
    uint32_t bAd[4];
    #pragma unroll
    for (int p = 0; p < 4; p++)
        bAd[p] = sbB + (uint32_t)((16 * p + ((lane >> 4) << 3) + (lane & 7)) * (BPAD * 4)
                                  + ((lane >> 3) & 1) * 16);

    float acc[2][8][4];
    // per-(thread,row) candidate shift-rings (4 newest within margin of local min)
    float lmin0 = INFINITY, lmin1 = INFINITY, lmin2 = INFINITY, lmin3 = INFINITY;
    float th0 = INFINITY, th1 = INFINITY, th2 = INFINITY, th3 = INFINITY;
    float rv0[4], rv1[4], rv2[4], rv3[4];
    int   ri0[4], ri1[4], ri2[4], ri3[4];
    int   rc0 = 0, rc1 = 0, rc2 = 0, rc3 = 0;

#define RING_PUSH(RV, RI, RC, LM, TH, sval, nval)                  \
    do {                                                           \
        if ((sval) < (TH)) {                                       \
            RV[3] = RV[2]; RI[3] = RI[2];                          \
            RV[2] = RV[1]; RI[2] = RI[1];                          \
            RV[1] = RV[0]; RI[1] = RI[0];                          \
            RV[0] = (sval); RI[0] = (nval); RC++;                  \
            if ((sval) < (LM)) { (LM) = (sval); (TH) = (sval) + MARGIN; } \
        }                                                          \
    } while (0)

    for (int c = 0; c < CHUNKS; c++) {
        // issue chunk c+1 into the other buffer
        if (c + 1 < CHUNKS) {
            const uint32_t base = sbB + (uint32_t)(((c + 1) & 1) * BUFB);
            const uint32_t* srcb = g_cbf + (size_t)(c + 1) * NC * (DIM / 2);
            #pragma unroll
            for (int it = 0; it < 8; it++) {
                int e = tid + 256 * it;
                int n = e >> 5, s4 = e & 31;
                cp_async16(base + (uint32_t)(n * (BPAD * 4) + s4 * 16),
                           srcb + (size_t)n * (DIM / 2) + s4 * 4);
            }
        }
        CP_COMMIT();
        if (c + 1 < CHUNKS) CP_WAIT1(); else CP_WAIT0();
        __syncthreads();                          // chunk c visible to all warps

        #pragma unroll
        for (int i = 0; i < 2; i++)
            #pragma unroll
            for (int j = 0; j < 8; j++)
                #pragma unroll
                for (int e = 0; e < 4; e++) acc[i][j][e] = 0.f;

        const uint32_t bufoff = (uint32_t)((c & 1) * BUFB);

        #pragma unroll
        for (int ks = 0; ks < 16; ks++) {
            const uint32_t koff = bufoff + ks * 32u;
            uint32_t Af0[4], Af1[4], Bf[4][4];
            ldsm4(Af0, aA0 + ks * 32u);
            ldsm4(Af1, aA1 + ks * 32u);
            ldsm4(Bf[0], bAd[0] + koff);
            ldsm4(Bf[1], bAd[1] + koff);
            ldsm4(Bf[2], bAd[2] + koff);
            ldsm4(Bf[3], bAd[3] + koff);
            #pragma unroll
            for (int j = 0; j < 8; j++) {
                uint32_t b0 = Bf[j >> 1][(j & 1) * 2];
                uint32_t b1 = Bf[j >> 1][(j & 1) * 2 + 1];
                mma_bf16(acc[0][j], Af0[0], Af0[1], Af0[2], Af0[3], b0, b1);
                mma_bf16(acc[1][j], Af1[0], Af1[1], Af1[2], Af1[3], b0, b1);
            }
        }

        // fold chunk scores into register rings
        const int cb0 = c * NC;
        #pragma unroll
        for (int j = 0; j < 8; j++) {
            int n0 = cb0 + j * 8 + 2 * t;
            float cn0 = cnS[n0], cn1 = cnS[n0 + 1];
            {   // i=0: rows rowbase (e0,e1), rowbase+8 (e2,e3)
                float s00 = fmaf(-2.f, acc[0][j][0], cn0);
                float s01 = fmaf(-2.f, acc[0][j][1], cn1);
                float s10 = fmaf(-2.f, acc[0][j][2], cn0);
                float s11 = fmaf(-2.f, acc[0][j][3], cn1);
                RING_PUSH(rv0, ri0, rc0, lmin0, th0, s00, n0);
                RING_PUSH(rv0, ri0, rc0, lmin0, th0, s01, n0 + 1);
                RING_PUSH(rv1, ri1, rc1, lmin1, th1, s10, n0);
                RING_PUSH(rv1, ri1, rc1, lmin1, th1, s11, n0 + 1);
            }
            {   // i=1: rows rowbase+16, rowbase+24
                float s00 = fmaf(-2.f, acc[1][j][0], cn0);
                float s01 = fmaf(-2.f, acc[1][j][1], cn1);
                float s10 = fmaf(-2.f, acc[1][j][2], cn0);
                float s11 = fmaf(-2.f, acc[1][j][3], cn1);
                RING_PUSH(rv2, ri2, rc2, lmin2, th2, s00, n0);
                RING_PUSH(rv2, ri2, rc2, lmin2, th2, s01, n0 + 1);
                RING_PUSH(rv3, ri3, rc3, lmin3, th3, s10, n0);
                RING_PUSH(rv3, ri3, rc3, lmin3, th3, s11, n0 + 1);
            }
        }
        __syncthreads();                          // all reads of buf c&1 done
    }

    // ---- merge: global per-row threshold ----
    atomicMin(&thrS[rowbase],      fkey(lmin0));
    atomicMin(&thrS[rowbase + 8],  fkey(lmin1));
    atomicMin(&thrS[rowbase + 16], fkey(lmin2));
    atomicMin(&thrS[rowbase + 24], fkey(lmin3));
    __syncthreads();

    // ---- filter-write candidates within gmin+MARGIN to shared (<= 8/token) ----
#define FILTER_ROW(RV, RI, RC, ROW)                                          \
    do {                                                                     \
        float thr = fdec(thrS[ROW]) + MARGIN;                                \
        int k = (RC < 4) ? RC : 4;                                           \
        _Pragma("unroll")                                                    \
        for (int sl = 0; sl < 4; sl++) {                                     \
            if (sl < k && RV[sl] <= thr) {                                   \
                uint32_t old = atomicAdd(&cntS[ROW], 1u);                    \
                if (old < 8) {                                               \
                    candv[(ROW) * 8 + old] = RV[sl];                         \
                    candi[(ROW) * 8 + old] = RI[sl];                         \
                }                                                            \
            }                                                                \
        }                                                                    \
    } while (0)
    FILTER_ROW(rv0, ri0, rc0, rowbase);
    FILTER_ROW(rv1, ri1, rc1, rowbase + 8);
    FILTER_ROW(rv2, ri2, rc2, rowbase + 16);
    FILTER_ROW(rv3, ri3, rc3, rowbase + 24);
    __syncthreads();

    // ---- final per-token selection + exact rescue (token m = tid) ----
    float tok_loss = 0.f;
    int   bei = 0;
    {
        const int m = tid;
        const float xn = xnS[m];
        uint32_t nv = cntS[m]; if (nv > 8) nv = 8;

        if (nv == 1) {
            bei = candi[m * 8];
            tok_loss = __fadd_rn(xn, candv[m * 8]);
        } else if (nv >= 2) {
            float bev = __int_as_float(0x7F800000);
            bei = 0x7fffffff;
            for (int base = 0; base < 8; base += 4) {
                if (base >= (int)nv) break;
                bool val[4]; int nn[4];
                #pragma unroll
                for (int q = 0; q < 4; q++) {
                    int sl = base + q;
                    bool v = (sl < (int)nv);
                    val[q] = v;
                    nn[q] = v ? candi[m * 8 + sl] : 0;
                }
                const float* p0 = cb + (size_t)nn[0] * DIM;
                const float* p1 = cb + (size_t)nn[1] * DIM;
                const float* p2 = cb + (size_t)nn[2] * DIM;
                const float* p3 = cb + (size_t)nn[3] * DIM;
                float a0 = 0.f, a1 = 0.f, a2 = 0.f, a3 = 0.f;
                #pragma unroll 8
                for (int d = 0; d < DIM; d++) {
                    float a = xb[(size_t)d * HW + m];    // exact f32 x
                    a0 = __fmaf_rn(a, p0[d], a0);
                    a1 = __fmaf_rn(a, p1[d], a1);
                    a2 = __fmaf_rn(a, p2[d], a2);
                    a3 = __fmaf_rn(a, p3[d], a3);
                }
                float accs[4] = {a0, a1, a2, a3};
                #pragma unroll
                for (int q = 0; q < 4; q++) {
                    if (!val[q]) continue;
                    float cn = cnS[nn[q]];
                    float t1 = __fadd_rn(xn, cn);
                    float se = __fadd_rn(t1, __fmul_rn(-2.f, accs[q]));
                    if (se < bev || (se == bev && nn[q] < bei)) { bev = se; bei = nn[q]; }
                }
            }
            tok_loss = bev;
        }
        // nv == 0 impossible (the global-min achiever always survives)

        int gt = t0 + m;
        g_idx[gt] = bei;
        out_idx_f[gt] = (float)bei;
        atomicAdd(&g_counts[bei], 1);
    }

    // ---- block loss reduction ----
    redS[tid] = tok_loss;
    __syncthreads();
    #pragma unroll
    for (int s = 128; s > 0; s >>= 1) {
        if (tid < s) redS[tid] += redS[tid + s];
        __syncthreads();
    }
    if (tid == 0) atomicAdd(&g_loss, (double)redS[0]);
}

// ---------------------------------------------------------------------------
// Gather quantized rows -> NCHW output (SMEM staged, fully coalesced)
// ---------------------------------------------------------------------------
#define GMT 128
#define CD  64
__global__ __launch_bounds__(256)
void gather_kernel(const float* __restrict__ cb, float* __restrict__ out_q) {
    __shared__ float qs[GMT][CD + 1];
    __shared__ int   sidx[GMT];
    const int tid  = threadIdx.x;
    const int t0   = blockIdx.x * GMT;
    const int b    = t0 >> 10;
    const int tloc = t0 & (HW - 1);
    float* ob = out_q + (size_t)b * DIM * HW + tloc;

    if (tid < GMT) sidx[tid] = g_idx[t0 + tid];
    __syncthreads();

    const int mm   = tid >> 1;
    const int part = (tid & 1) * 32;

    for (int d0 = 0; d0 < DIM; d0 += CD) {
        const float4* src = (const float4*)(cb + (size_t)sidx[mm] * DIM + d0 + part);
        #pragma unroll
        for (int q = 0; q < 8; q++) {
            float4 v = src[q];
            int dd = part + q * 4;
            qs[mm][dd + 0] = v.x; qs[mm][dd + 1] = v.y;
            qs[mm][dd + 2] = v.z; qs[mm][dd + 3] = v.w;
        }
        __syncthreads();
        #pragma unroll
        for (int j = 0; j < (GMT * CD) / 256; j++) {
            int i = tid + 256 * j;
            int d = i >> 7, m2 = i & 127;
            ob[(size_t)(d0 + d) * HW + m2] = qs[m2][d];
        }
        __syncthreads();
    }
}

// ---------------------------------------------------------------------------
// Finalize: loss + perplexity
// ---------------------------------------------------------------------------
__global__ void finalize_kernel(float* __restrict__ out_loss,
                                float* __restrict__ out_perp) {
    __shared__ float sred[KCODE];
    int t = threadIdx.x;
    float p = (float)g_counts[t] / (float)NTOK;
    sred[t] = p * logf(p + 1e-10f);
    __syncthreads();
    #pragma unroll
    for (int s = 512; s > 0; s >>= 1) {
        if (t < s) sred[t] += sred[t + s];
        __syncthreads();
    }
    if (t == 0) {
        out_perp[0] = expf(-sred[0]);
        out_loss[0] = (float)(1.25 * g_loss / ((double)NTOK * (double)DIM));
    }
}

// ---------------------------------------------------------------------------
extern "C" void kernel_launch(void* const* d_in, const int* in_sizes, int n_in,
                              void* d_out, int out_size) {
    const float* x  = (const float*)d_in[0];
    const float* cb = (const float*)d_in[1];
    if (n_in >= 2 && in_sizes[0] < in_sizes[1]) {
        const float* t = x; x = cb; cb = t;
    }

    float* out      = (float*)d_out;
    float* out_loss = out;
    float* out_q    = out + 1;
    float* out_perp = out + 1 + (size_t)NTOK * DIM;
    float* out_idx  = out + 2 + (size_t)NTOK * DIM;

    static int attr_done = 0;
    if (!attr_done) {
        cudaFuncSetAttribute(argmin_kernel, cudaFuncAttributeMaxDynamicSharedMemorySize, SMEM_TOTAL);
        attr_done = 1;
    }

    prep_kernel   <<<4, 256>>>(cb);
    argmin_kernel <<<NTOK / MT, 256, SMEM_TOTAL>>>(x, cb, out_idx);
    gather_kernel <<<NTOK / GMT, 256>>>(cb, out_q);
    finalize_kernel<<<1, KCODE>>>(out_loss, out_perp);
}

// round 8
// speedup vs baseline: 1.0804x; 1.0804x over previous
#include <cuda_runtime.h>
#include <math.h>
#include <stdint.h>

// Problem constants
#define NTOK   65536
#define DIM    256
#define KCODE  1024
#define HW     1024
#define MT     128          // tokens per CTA
#define NC     32           // codes per B chunk
#define CHUNKS 32
#define MARGIN 8.0e-4f
#define NSLOT  6            // shared candidate slots per token
#define APAD   132          // u32 (bf16x2) per A row (128 + 4 pad) -> 528B stride
#define BPAD   132          // u32 (bf16x2) per B row
#define BUFB   (NC*BPAD*4)  // 16896 bytes per B buffer

// smem byte offsets (total 113152 <= 113664 for 2 CTAs/SM)
#define OFF_A     0                             // 128*132*4 = 67584
#define OFF_B     67584                         // 2*32*132*4 = 33792
#define OFF_CN    101376                        // 1024 f32 = 4096
#define OFF_CANDV 105472                        // 128*6 f32 = 3072 (aliased as red later)
#define OFF_CANDI 108544                        // 128*6 i32 = 3072
#define OFF_THR   111616                        // 128 u32
#define OFF_CNT   112128                        // 128 u32
#define OFF_XN    112640                        // 128 f32
#define SMEM_TOTAL 113152

__device__ __align__(16) float    g_cnorm[KCODE];
__device__ __align__(16) uint32_t g_cbf[KCODE * DIM / 2];   // bf16 codebook
__device__ int    g_idx[NTOK];
__device__ int    g_counts[KCODE];
__device__ double g_loss;

// ---------------- helpers ----------------
__device__ __forceinline__ uint32_t smem_u32(const void* p) {
    uint32_t a;
    asm("{ .reg .u64 t; cvta.to.shared.u64 t, %1; cvt.u32.u64 %0, t; }" : "=r"(a) : "l"(p));
    return a;
}
__device__ __forceinline__ uint32_t fkey(float f) {
    uint32_t u = __float_as_uint(f);
    return u ^ (uint32_t)(((int32_t)u >> 31) | 0x80000000);
}
__device__ __forceinline__ float fdec(uint32_t k) {
    uint32_t u = (k & 0x80000000u) ? (k ^ 0x80000000u) : ~k;
    return __uint_as_float(u);
}
__device__ __forceinline__ uint32_t packbf(float lo, float hi) {
    uint32_t r;
    asm("cvt.rn.bf16x2.f32 %0, %1, %2;" : "=r"(r) : "f"(hi), "f"(lo));
    return r;
}
__device__ __forceinline__ void mma_bf16(float* c, uint32_t a0, uint32_t a1,
                                         uint32_t a2, uint32_t a3,
                                         uint32_t b0, uint32_t b1) {
    asm volatile("mma.sync.aligned.m16n8k16.row.col.f32.bf16.bf16.f32 "
                 "{%0,%1,%2,%3}, {%4,%5,%6,%7}, {%8,%9}, {%0,%1,%2,%3};"
                 : "+f"(c[0]), "+f"(c[1]), "+f"(c[2]), "+f"(c[3])
                 : "r"(a0), "r"(a1), "r"(a2), "r"(a3), "r"(b0), "r"(b1));
}
__device__ __forceinline__ void cp_async16(uint32_t dst, const void* src) {
    asm volatile("cp.async.cg.shared.global [%0], [%1], 16;"
                 :: "r"(dst), "l"(__cvta_generic_to_global(src)) : "memory");
}
#define CP_COMMIT() asm volatile("cp.async.commit_group;" ::: "memory")
#define CP_WAIT1()  asm volatile("cp.async.wait_group 1;" ::: "memory")
#define CP_WAIT0()  asm volatile("cp.async.wait_group 0;" ::: "memory")

// ---------------------------------------------------------------------------
// Kernel A: sequential fp32 codebook norms (bit-identical to ref reduce) +
// bf16 codebook conversion + zero accumulators.
// ---------------------------------------------------------------------------
__global__ void prep_kernel(const float* __restrict__ cb) {
    int gid = blockIdx.x * blockDim.x + threadIdx.x;
    if (gid < KCODE) {
        const float4* row = (const float4*)(cb + (size_t)gid * DIM);
        uint32_t* dst = g_cbf + (size_t)gid * (DIM / 2);
        float s = 0.f;
        #pragma unroll 4
        for (int q = 0; q < DIM / 4; q++) {
            float4 v = row[q];
            s = __fadd_rn(s, __fmul_rn(v.x, v.x));
            s = __fadd_rn(s, __fmul_rn(v.y, v.y));
            s = __fadd_rn(s, __fmul_rn(v.z, v.z));
            s = __fadd_rn(s, __fmul_rn(v.w, v.w));
            dst[2 * q]     = packbf(v.x, v.y);
            dst[2 * q + 1] = packbf(v.z, v.w);
        }
        g_cnorm[gid] = s;
        g_counts[gid] = 0;
    }
    if (gid == 0) g_loss = 0.0;
}

// ---------------------------------------------------------------------------
// Main fused kernel: bf16 mma.sync + register candidate rings + exact fp32
// rescue + argmin + histogram + loss.  512 CTAs x 256 threads, 2 CTAs/SM.
// Each warp: m16 token rows x full 32-code chunk; 32 chunks.
// ---------------------------------------------------------------------------
__global__ __launch_bounds__(256, 2)
void argmin_kernel(const float* __restrict__ x, const float* __restrict__ cb,
                   float* __restrict__ out_idx_f) {
    extern __shared__ char smem[];
    uint32_t* Au    = (uint32_t*)(smem + OFF_A);
    uint32_t* Bu0   = (uint32_t*)(smem + OFF_B);
    float*    cnS   = (float*)(smem + OFF_CN);
    float*    candv = (float*)(smem + OFF_CANDV);
    int*      candi = (int*)(smem + OFF_CANDI);
    uint32_t* thrS  = (uint32_t*)(smem + OFF_THR);
    uint32_t* cntS  = (uint32_t*)(smem + OFF_CNT);
    float*    xnS   = (float*)(smem + OFF_XN);

    const uint32_t sbB = smem_u32(smem + OFF_B);

    const int tid  = threadIdx.x;
    const int lane = tid & 31;
    const int wid  = tid >> 5;
    const int g    = lane >> 2;
    const int t    = lane & 3;

    const int t0   = blockIdx.x * MT;
    const int b    = t0 >> 10;
    const int tloc = t0 & (HW - 1);
    const float* xb = x + (size_t)b * DIM * HW + tloc;   // (d,m): xb[d*HW+m]

    // ---- issue B chunk 0 cp.async (overlaps A pass) ----
    {
        #pragma unroll
        for (int it = 0; it < 4; it++) {
            int e = tid + 256 * it;               // 0..1023 = 32 rows x 32 x 16B
            int n = e >> 5, s4 = e & 31;
            cp_async16(sbB + (uint32_t)(n * (BPAD * 4) + s4 * 16),
                       g_cbf + (size_t)n * (DIM / 2) + s4 * 4);
        }
        CP_COMMIT();
    }

    // ---- per-token init ----
    if (tid < MT) {
        thrS[tid] = 0xFF800000u;    // fkey(+inf)
        cntS[tid] = 0;
    }
    ((float4*)cnS)[tid] = ((const float4*)g_cnorm)[tid];

    // ---- A pass: exact sequential xn + bf16 A tile (tid < 128 = token) ----
    if (tid < MT) {
        const float* xp = xb + tid;
        float xn = 0.f, prev = 0.f;
        #pragma unroll 8
        for (int d = 0; d < DIM; d++) {
            float v = xp[(size_t)d * HW];
            xn = __fadd_rn(xn, __fmul_rn(v, v));
            if (d & 1) Au[tid * APAD + (d >> 1)] = packbf(prev, v);
            else prev = v;
        }
        xnS[tid] = xn;
    }
    __syncthreads();

    // ---- MMA setup: warp covers rows [wid*16, wid*16+16) ----
    const int rowbase = wid * 16 + g;             // thread rows: rowbase, rowbase+8
    uint32_t* Ap = Au + (wid * 16 + g) * APAD + t;

    float acc[4][4];
    float lmin0 = INFINITY, lmin1 = INFINITY;
    float th0 = INFINITY, th1 = INFINITY;
    float rv0[4], rv1[4];
    int   ri0[4], ri1[4];
    int   rc0 = 0, rc1 = 0;

#define RING_PUSH(RV, RI, RC, LM, TH, sval, nval)                  \
    do {                                                           \
        if ((sval) < (TH)) {                                       \
            RV[3] = RV[2]; RI[3] = RI[2];                          \
            RV[2] = RV[1]; RI[2] = RI[1];                          \
            RV[1] = RV[0]; RI[1] = RI[0];                          \
            RV[0] = (sval); RI[0] = (nval); RC++;                  \
            if ((sval) < (LM)) { (LM) = (sval); (TH) = (sval) + MARGIN; } \
        }                                                          \
    } while (0)

    for (int c = 0; c < CHUNKS; c++) {
        // issue chunk c+1 into the other buffer
        if (c + 1 < CHUNKS) {
            const uint32_t base = sbB + (uint32_t)(((c + 1) & 1) * BUFB);
            const uint32_t* srcb = g_cbf + (size_t)(c + 1) * NC * (DIM / 2);
            #pragma unroll
            for (int it = 0; it < 4; it++) {
                int e = tid + 256 * it;
                int n = e >> 5, s4 = e & 31;
                cp_async16(base + (uint32_t)(n * (BPAD * 4) + s4 * 16),
                           srcb + (size_t)n * (DIM / 2) + s4 * 4);
            }
        }
        CP_COMMIT();
        if (c + 1 < CHUNKS) CP_WAIT1(); else CP_WAIT0();
        __syncthreads();                          // chunk c visible to all warps

        #pragma unroll
        for (int j = 0; j < 4; j++)
            #pragma unroll
            for (int e = 0; e < 4; e++) acc[j][e] = 0.f;

        uint32_t* Br = Bu0 + (c & 1) * (NC * BPAD) + g * BPAD + t;

        #pragma unroll
        for (int ks = 0; ks < 16; ks++) {
            const int col = ks * 8;               // u32 column
            uint32_t a0 = Ap[col],     a1 = Ap[8 * APAD + col];
            uint32_t a2 = Ap[col + 4], a3 = Ap[8 * APAD + col + 4];
            uint32_t b0[4], b1[4];
            #pragma unroll
            for (int j = 0; j < 4; j++) {
                b0[j] = Br[j * 8 * BPAD + col];
                b1[j] = Br[j * 8 * BPAD + col + 4];
            }
            #pragma unroll
            for (int j = 0; j < 4; j++)
                mma_bf16(acc[j], a0, a1, a2, a3, b0[j], b1[j]);
        }

        // fold chunk scores into register rings
        const int cb0 = c * NC;
        #pragma unroll
        for (int j = 0; j < 4; j++) {
            int n0 = cb0 + j * 8 + 2 * t;
            float cn0 = cnS[n0], cn1 = cnS[n0 + 1];
            float s00 = fmaf(-2.f, acc[j][0], cn0);
            float s01 = fmaf(-2.f, acc[j][1], cn1);
            float s10 = fmaf(-2.f, acc[j][2], cn0);
            float s11 = fmaf(-2.f, acc[j][3], cn1);
            RING_PUSH(rv0, ri0, rc0, lmin0, th0, s00, n0);
            RING_PUSH(rv0, ri0, rc0, lmin0, th0, s01, n0 + 1);
            RING_PUSH(rv1, ri1, rc1, lmin1, th1, s10, n0);
            RING_PUSH(rv1, ri1, rc1, lmin1, th1, s11, n0 + 1);
        }
        __syncthreads();                          // all reads of buf c&1 done
    }

    // ---- merge: global per-row threshold ----
    atomicMin(&thrS[rowbase],     fkey(lmin0));
    atomicMin(&thrS[rowbase + 8], fkey(lmin1));
    __syncthreads();

    // ---- filter-write candidates within gmin+MARGIN to shared ----
#define FILTER_ROW(RV, RI, RC, ROW)                                          \
    do {                                                                     \
        float thr = fdec(thrS[ROW]) + MARGIN;                                \
        int k = (RC < 4) ? RC : 4;                                           \
        _Pragma("unroll")                                                    \
        for (int sl = 0; sl < 4; sl++) {                                     \
            if (sl < k && RV[sl] <= thr) {                                   \
                uint32_t old = atomicAdd(&cntS[ROW], 1u);                    \
                if (old < NSLOT) {                                           \
                    candv[(ROW) * NSLOT + old] = RV[sl];                     \
                    candi[(ROW) * NSLOT + old] = RI[sl];                     \
                }                                                            \
            }                                                                \
        }                                                                    \
    } while (0)
    FILTER_ROW(rv0, ri0, rc0, rowbase);
    FILTER_ROW(rv1, ri1, rc1, rowbase + 8);
    __syncthreads();

    // ---- final per-token selection + exact rescue (token m = tid < 128) ----
    float tok_loss = 0.f;
    if (tid < MT) {
        const int m = tid;
        const float xn = xnS[m];
        uint32_t nv = cntS[m]; if (nv > NSLOT) nv = NSLOT;
        int bei = 0;

        if (nv == 1) {
            bei = candi[m * NSLOT];
            tok_loss = __fadd_rn(xn, candv[m * NSLOT]);
        } else if (nv >= 2) {
            float bev = __int_as_float(0x7F800000);
            bei = 0x7fffffff;
            for (int base = 0; base < NSLOT; base += 4) {
                if (base >= (int)nv) break;
                bool val[4]; int nn[4];
                #pragma unroll
                for (int q = 0; q < 4; q++) {
                    int sl = base + q;
                    bool v = (sl < (int)nv) && (sl < NSLOT);
                    val[q] = v;
                    nn[q] = v ? candi[m * NSLOT + sl] : 0;
                }
                const float* p0 = cb + (size_t)nn[0] * DIM;
                const float* p1 = cb + (size_t)nn[1] * DIM;
                const float* p2 = cb + (size_t)nn[2] * DIM;
                const float* p3 = cb + (size_t)nn[3] * DIM;
                float a0 = 0.f, a1 = 0.f, a2 = 0.f, a3 = 0.f;
                #pragma unroll 8
                for (int d = 0; d < DIM; d++) {
                    float a = xb[(size_t)d * HW + m];    // exact f32 x
                    a0 = __fmaf_rn(a, p0[d], a0);
                    a1 = __fmaf_rn(a, p1[d], a1);
                    a2 = __fmaf_rn(a, p2[d], a2);
                    a3 = __fmaf_rn(a, p3[d], a3);
                }
                float accs[4] = {a0, a1, a2, a3};
                #pragma unroll
                for (int q = 0; q < 4; q++) {
                    if (!val[q]) continue;
                    float cn = cnS[nn[q]];
                    float t1 = __fadd_rn(xn, cn);
                    float se = __fadd_rn(t1, __fmul_rn(-2.f, accs[q]));
                    if (se < bev || (se == bev && nn[q] < bei)) { bev = se; bei = nn[q]; }
                }
            }
            tok_loss = bev;
        }
        // nv == 0 impossible (the global-min achiever always survives)

        int gt = t0 + m;
        g_idx[gt] = bei;
        out_idx_f[gt] = (float)bei;
        atomicAdd(&g_counts[bei], 1);
    }

    // ---- block loss reduction (aliased onto candv region) ----
    __syncthreads();
    float* redS = candv;                          // 256 f32 fit in 768-slot region
    redS[tid] = tok_loss;
    __syncthreads();
    #pragma unroll
    for (int s = 128; s > 0; s >>= 1) {
        if (tid < s) redS[tid] += redS[tid + s];
        __syncthreads();
    }
    if (tid == 0) atomicAdd(&g_loss, (double)redS[0]);
}

// ---------------------------------------------------------------------------
// Gather quantized rows -> NCHW output (SMEM staged, fully coalesced)
// ---------------------------------------------------------------------------
#define GMT 128
#define CD  64
__global__ __launch_bounds__(256)
void gather_kernel(const float* __restrict__ cb, float* __restrict__ out_q) {
    __shared__ float qs[GMT][CD + 1];
    __shared__ int   sidx[GMT];
    const int tid  = threadIdx.x;
    const int t0   = blockIdx.x * GMT;
    const int b    = t0 >> 10;
    const int tloc = t0 & (HW - 1);
    float* ob = out_q + (size_t)b * DIM * HW + tloc;

    if (tid < GMT) sidx[tid] = g_idx[t0 + tid];
    __syncthreads();

    const int mm   = tid >> 1;
    const int part = (tid & 1) * 32;

    for (int d0 = 0; d0 < DIM; d0 += CD) {
        const float4* src = (const float4*)(cb + (size_t)sidx[mm] * DIM + d0 + part);
        #pragma unroll
        for (int q = 0; q < 8; q++) {
            float4 v = src[q];
            int dd = part + q * 4;
            qs[mm][dd + 0] = v.x; qs[mm][dd + 1] = v.y;
            qs[mm][dd + 2] = v.z; qs[mm][dd + 3] = v.w;
        }
        __syncthreads();
        #pragma unroll
        for (int j = 0; j < (GMT * CD) / 256; j++) {
            int i = tid + 256 * j;
            int d = i >> 7, m2 = i & 127;
            ob[(size_t)(d0 + d) * HW + m2] = qs[m2][d];
        }
        __syncthreads();
    }
}

// ---------------------------------------------------------------------------
// Finalize: loss + perplexity
// ---------------------------------------------------------------------------
__global__ void finalize_kernel(float* __restrict__ out_loss,
                                float* __restrict__ out_perp) {
    __shared__ float sred[KCODE];
    int t = threadIdx.x;
    float p = (float)g_counts[t] / (float)NTOK;
    sred[t] = p * logf(p + 1e-10f);
    __syncthreads();
    #pragma unroll
    for (int s = 512; s > 0; s >>= 1) {
        if (t < s) sred[t] += sred[t + s];
        __syncthreads();
    }
    if (t == 0) {
        out_perp[0] = expf(-sred[0]);
        out_loss[0] = (float)(1.25 * g_loss / ((double)NTOK * (double)DIM));
    }
}

// ---------------------------------------------------------------------------
extern "C" void kernel_launch(void* const* d_in, const int* in_sizes, int n_in,
                              void* d_out, int out_size) {
    const float* x  = (const float*)d_in[0];
    const float* cb = (const float*)d_in[1];
    if (n_in >= 2 && in_sizes[0] < in_sizes[1]) {
        const float* t = x; x = cb; cb = t;
    }

    float* out      = (float*)d_out;
    float* out_loss = out;
    float* out_q    = out + 1;
    float* out_perp = out + 1 + (size_t)NTOK * DIM;
    float* out_idx  = out + 2 + (size_t)NTOK * DIM;

    static int attr_done = 0;
    if (!attr_done) {
        cudaFuncSetAttribute(argmin_kernel, cudaFuncAttributeMaxDynamicSharedMemorySize, SMEM_TOTAL);
        attr_done = 1;
    }

    prep_kernel   <<<4, 256>>>(cb);
    argmin_kernel <<<NTOK / MT, 256, SMEM_TOTAL>>>(x, cb, out_idx);
    gather_kernel <<<NTOK / GMT, 256>>>(cb, out_q);
    finalize_kernel<<<1, KCODE>>>(out_loss, out_perp);
}